// round 11
// baseline (speedup 1.0000x reference)
#include <cuda_runtime.h>
#include <cuda_bf16.h>
#include <cuda_fp16.h>
#include <mma.h>
#include <cstdint>

using namespace nvcuda;

#define MAXN 50048
#define HID 128
#define MAXG 2048
#define MAXDEG 128

// Scratch (device globals; allocation is forbidden)
__device__ __half g_aggh[(size_t)MAXN * HID];
__device__ __half g_th [(size_t)MAXN * HID];   // fp16 intra-layer intermediate
__device__ __half g_xh [(size_t)MAXN * HID];
__device__ __half g_hh [(size_t)MAXN * HID];
__device__ float  g_h2 [(size_t)MAXN * HID];
__device__ int    g_cur[MAXN];
__device__ int    g_esrc[(size_t)MAXN * MAXDEG];
__device__ __half g_Wh[4][HID * HID];
__device__ __half g_Wl[4][HID * HID];

// ---------------------------------------------------------------------------
// Fused prep kernel: (a) padded-bucket edge fill, (b) x fp32->fp16,
// (c) weight pre-split. Independent jobs partitioned by blockIdx range.
// ---------------------------------------------------------------------------
__global__ __launch_bounds__(256) void prep_kernel(
    const int* __restrict__ src, const int* __restrict__ dst,
    int* __restrict__ cur, int* __restrict__ esrc, int E, int fill_blocks,
    const float* __restrict__ x, __half* __restrict__ xh, int n8, int f2h_blocks,
    const float* __restrict__ W1a, const float* __restrict__ W1b,
    const float* __restrict__ W2a, const float* __restrict__ W2b,
    __half* __restrict__ Wh, __half* __restrict__ Wl)
{
    int b = blockIdx.x;
    if (b < fill_blocks) {
        int e = b * 256 + threadIdx.x;
        if (e < E) {
            int d = dst[e];
            int pos = atomicAdd(&cur[d], 1);
            if (pos < MAXDEG) esrc[(size_t)d * MAXDEG + pos] = src[e];
        }
    } else if (b < fill_blocks + f2h_blocks) {
        int i = (b - fill_blocks) * 256 + threadIdx.x;
        if (i < n8) {
            float4 a = *reinterpret_cast<const float4*>(x + (size_t)i * 8);
            float4 c = *reinterpret_cast<const float4*>(x + (size_t)i * 8 + 4);
            uint4 u;
            *reinterpret_cast<__half2*>(&u.x) = __floats2half2_rn(a.x, a.y);
            *reinterpret_cast<__half2*>(&u.y) = __floats2half2_rn(a.z, a.w);
            *reinterpret_cast<__half2*>(&u.z) = __floats2half2_rn(c.x, c.y);
            *reinterpret_cast<__half2*>(&u.w) = __floats2half2_rn(c.z, c.w);
            *reinterpret_cast<uint4*>(xh + (size_t)i * 8) = u;
        }
    } else {
        int i = (b - fill_blocks - f2h_blocks) * 256 + threadIdx.x;
        if (i < 4 * HID * HID) {
            int plane = i >> 14, idx = i & 16383;
            const float* s = (plane == 0) ? W1a : (plane == 1) ? W1b
                           : (plane == 2) ? W2a : W2b;
            float v = s[idx];
            __half h = __float2half(v);
            __half l = __float2half(v - __half2float(h));
            Wh[i] = h;
            Wl[i] = l;
        }
    }
}

// ---------------------------------------------------------------------------
// Gather aggregation (fp16 in, fp16 out) — at its roofline; unchanged.
// ---------------------------------------------------------------------------
__device__ __forceinline__ void acc_row(const uint4& u, float4& a, float4& b)
{
    float2 f;
    f = __half22float2(*reinterpret_cast<const __half2*>(&u.x)); a.x += f.x; a.y += f.y;
    f = __half22float2(*reinterpret_cast<const __half2*>(&u.y)); a.z += f.x; a.w += f.y;
    f = __half22float2(*reinterpret_cast<const __half2*>(&u.z)); b.x += f.x; b.y += f.y;
    f = __half22float2(*reinterpret_cast<const __half2*>(&u.w)); b.z += f.x; b.w += f.y;
}

__global__ __launch_bounds__(256) void gather_agg_h_kernel(
    const __half* __restrict__ xh, const int* __restrict__ esrc,
    const int* __restrict__ deg_arr, __half* __restrict__ out, int Nn)
{
    int node = blockIdx.x * 16 + (threadIdx.x >> 4);
    int l16  = threadIdx.x & 15;
    if (node >= Nn) return;
    int deg = min(deg_arr[node], MAXDEG);
    const int* row = esrc + (size_t)node * MAXDEG;
    const int col = l16 * 8;

    float4 accA = make_float4(0.f, 0.f, 0.f, 0.f);
    float4 accB = make_float4(0.f, 0.f, 0.f, 0.f);
    {
        uint4 u = *reinterpret_cast<const uint4*>(xh + (size_t)node * HID + col);
        acc_row(u, accA, accB);
    }
    int e = 0;
    for (; e + 4 <= deg; e += 4) {
        int4 s = *reinterpret_cast<const int4*>(row + e);
        uint4 u0 = *reinterpret_cast<const uint4*>(xh + (size_t)s.x * HID + col);
        uint4 u1 = *reinterpret_cast<const uint4*>(xh + (size_t)s.y * HID + col);
        uint4 u2 = *reinterpret_cast<const uint4*>(xh + (size_t)s.z * HID + col);
        uint4 u3 = *reinterpret_cast<const uint4*>(xh + (size_t)s.w * HID + col);
        acc_row(u0, accA, accB);
        acc_row(u1, accA, accB);
        acc_row(u2, accA, accB);
        acc_row(u3, accA, accB);
    }
    for (; e < deg; e++) {
        int s = __ldg(row + e);
        uint4 u = *reinterpret_cast<const uint4*>(xh + (size_t)s * HID + col);
        acc_row(u, accA, accB);
    }
    uint4 o;
    *reinterpret_cast<__half2*>(&o.x) = __floats2half2_rn(accA.x, accA.y);
    *reinterpret_cast<__half2*>(&o.y) = __floats2half2_rn(accA.z, accA.w);
    *reinterpret_cast<__half2*>(&o.z) = __floats2half2_rn(accB.x, accB.y);
    *reinterpret_cast<__half2*>(&o.w) = __floats2half2_rn(accB.z, accB.w);
    *reinterpret_cast<uint4*>(out + (size_t)node * HID + col) = o;
}

// ---------------------------------------------------------------------------
// Single GEMM: out = relu(A @ W + b).  W as fp16 hi+lo planes (2-term split).
// Block = 256 threads, tile 128 rows x 64 cols; warp tile 32x32 (acc = 4 frags
// = 32 regs -> low register pressure -> 3+ CTAs/SM).  grid = (rows/128, 2).
// Static smem 19.5 KB: Ah[128][40] | Bh[32][72] | Bl[32][72]; stage aliases Ah.
// ---------------------------------------------------------------------------
__global__ __launch_bounds__(256) void gemm_h_kernel(
    const __half* __restrict__ A,
    const __half* __restrict__ Wh_, const __half* __restrict__ Wl_,
    const float* __restrict__ bias,
    float* __restrict__ Cf, __half* __restrict__ Ch, int Nrows)
{
    __shared__ __half Ah[128 * 40];
    __shared__ __half Bh[32 * 72];
    __shared__ __half Bl[32 * 72];

    const int tid  = threadIdx.x;
    const int warp = tid >> 5;
    const int lane = tid & 31;
    const int wm = warp >> 1;          // 0..3  (32-row group)
    const int wn = warp & 1;           // 0..1  (32-col group)
    const int row0 = blockIdx.x * 128;
    const int col0 = blockIdx.y * 64;  // column half of the 128-wide output
    float* stage = reinterpret_cast<float*>(Ah) + warp * 320;   // 16x20 per warp

    wmma::fragment<wmma::accumulator, 16, 16, 16, float> acc[2][2];
    #pragma unroll
    for (int i = 0; i < 2; i++)
        #pragma unroll
        for (int j = 0; j < 2; j++) wmma::fill_fragment(acc[i][j], 0.0f);

    for (int kc = 0; kc < 128; kc += 32) {
        // A tile: 128 rows x 32 halfs = 512 uint4
        #pragma unroll
        for (int i = tid; i < 512; i += 256) {
            int r = i >> 2, c8 = (i & 3) * 8;
            int gr = row0 + r;
            uint4 u = make_uint4(0u, 0u, 0u, 0u);
            if (gr < Nrows)
                u = *reinterpret_cast<const uint4*>(A + (size_t)gr * HID + kc + c8);
            *reinterpret_cast<uint4*>(Ah + r * 40 + c8) = u;
        }
        // W tiles: 32 rows x 64 halfs per plane = 256 uint4 each
        {
            int r = tid >> 3, c8 = (tid & 7) * 8;
            size_t goff = (size_t)(kc + r) * HID + col0 + c8;
            *reinterpret_cast<uint4*>(Bh + r * 72 + c8) =
                *reinterpret_cast<const uint4*>(Wh_ + goff);
            *reinterpret_cast<uint4*>(Bl + r * 72 + c8) =
                *reinterpret_cast<const uint4*>(Wl_ + goff);
        }
        __syncthreads();

        #pragma unroll
        for (int kk = 0; kk < 32; kk += 16) {
            wmma::fragment<wmma::matrix_a, 16, 16, 16, __half, wmma::row_major> a[2];
            wmma::fragment<wmma::matrix_b, 16, 16, 16, __half, wmma::row_major> bh[2], bl[2];
            #pragma unroll
            for (int i = 0; i < 2; i++)
                wmma::load_matrix_sync(a[i], Ah + (wm * 32 + i * 16) * 40 + kk, 40);
            #pragma unroll
            for (int j = 0; j < 2; j++) {
                wmma::load_matrix_sync(bh[j], Bh + kk * 72 + wn * 32 + j * 16, 72);
                wmma::load_matrix_sync(bl[j], Bl + kk * 72 + wn * 32 + j * 16, 72);
            }
            #pragma unroll
            for (int i = 0; i < 2; i++)
                #pragma unroll
                for (int j = 0; j < 2; j++) {
                    wmma::mma_sync(acc[i][j], a[i], bl[j], acc[i][j]);
                    wmma::mma_sync(acc[i][j], a[i], bh[j], acc[i][j]);
                }
        }
        __syncthreads();
    }

    // epilogue: bias + relu -> fp16 and/or fp32 (stage aliases Ah)
    #pragma unroll
    for (int i = 0; i < 2; i++) {
        #pragma unroll
        for (int j = 0; j < 2; j++) {
            wmma::store_matrix_sync(stage, acc[i][j], 20, wmma::mem_row_major);
            __syncwarp();
            #pragma unroll
            for (int e = lane; e < 256; e += 32) {
                int r = e >> 4, c = e & 15;
                int gr = row0 + wm * 32 + i * 16 + r;
                int gc = col0 + wn * 32 + j * 16 + c;
                if (gr < Nrows) {
                    float v = fmaxf(stage[r * 20 + c] + bias[gc], 0.0f);
                    size_t idx = (size_t)gr * HID + gc;
                    if (Ch) Ch[idx] = __float2half(v);
                    else    Cf[idx] = v;
                }
            }
            __syncwarp();
        }
    }
}

// ---------------------------------------------------------------------------
// Fused pool + head (batch sorted -> contiguous ranges, no atomics)
// ---------------------------------------------------------------------------
__global__ __launch_bounds__(128) void pool_head_kernel(
    const float* __restrict__ h,
    const int* __restrict__ batch, int Nn,
    const float* __restrict__ Ws, const float* __restrict__ bs,
    const float* __restrict__ WlS, const float* __restrict__ blS,
    const float* __restrict__ WlP, const float* __restrict__ blP,
    const float* __restrict__ WnR, const float* __restrict__ bnR,
    float* __restrict__ out, int G)
{
    __shared__ float p[128];
    __shared__ float gv[64];
    const int g = blockIdx.x;
    const int tid = threadIdx.x;

    int lo = 0, hi = Nn;
    while (lo < hi) { int m = (lo + hi) >> 1; if (batch[m] < g) lo = m + 1; else hi = m; }
    int start = lo;
    hi = Nn;
    while (lo < hi) { int m = (lo + hi) >> 1; if (batch[m] < g + 1) lo = m + 1; else hi = m; }
    int end = lo;

    float s = 0.0f;
    for (int i = start; i < end; i++)
        s += h[(size_t)i * HID + tid];
    float inv = 1.0f / fmaxf((float)(end - start), 1.0f);
    p[tid] = s * inv;
    __syncthreads();

    if (tid < 64) {
        float acc = bs[tid];
        #pragma unroll 8
        for (int k = 0; k < 128; k++) acc += p[k] * Ws[k * 64 + tid];
        gv[tid] = fmaxf(acc, 0.0f);
    }
    __syncthreads();

    if (tid < 3) {
        const float* w = (tid == 0) ? WlS : (tid == 1) ? WlP : WnR;
        float acc = (tid == 0) ? blS[0] : (tid == 1) ? blP[0] : bnR[0];
        #pragma unroll 8
        for (int j = 0; j < 64; j++) acc += gv[j] * w[j];
        out[(size_t)tid * G + g] = acc;
    }
}

// ---------------------------------------------------------------------------
// Launch
// ---------------------------------------------------------------------------
extern "C" void kernel_launch(void* const* d_in, const int* in_sizes, int n_in,
                              void* d_out, int out_size)
{
    const float* x     = (const float*)d_in[0];
    const int*   ei    = (const int*)d_in[1];
    const int*   batch = (const int*)d_in[2];
    const float* W1a = (const float*)d_in[3];
    const float* b1a = (const float*)d_in[4];
    const float* W1b = (const float*)d_in[5];
    const float* b1b = (const float*)d_in[6];
    const float* W2a = (const float*)d_in[7];
    const float* b2a = (const float*)d_in[8];
    const float* W2b = (const float*)d_in[9];
    const float* b2b = (const float*)d_in[10];
    const float* Ws  = (const float*)d_in[11];
    const float* bs  = (const float*)d_in[12];
    const float* WlS = (const float*)d_in[13];
    const float* blS = (const float*)d_in[14];
    const float* WlP = (const float*)d_in[15];
    const float* blP = (const float*)d_in[16];
    const float* WnR = (const float*)d_in[17];
    const float* bnR = (const float*)d_in[18];
    float* out = (float*)d_out;

    const int Nn = in_sizes[0] / HID;      // 50000
    const int E  = in_sizes[1] / 2;        // 1600000
    const int G  = out_size / 3;           // 2048
    const int*   src = ei;
    const int*   dst = ei + E;

    float *h2;
    __half *aggh, *th, *xh, *hh, *Wh, *Wl;
    int *cur, *esrc;
    cudaGetSymbolAddress((void**)&aggh,   g_aggh);
    cudaGetSymbolAddress((void**)&th,     g_th);
    cudaGetSymbolAddress((void**)&xh,     g_xh);
    cudaGetSymbolAddress((void**)&hh,     g_hh);
    cudaGetSymbolAddress((void**)&h2,     g_h2);
    cudaGetSymbolAddress((void**)&cur,    g_cur);
    cudaGetSymbolAddress((void**)&esrc,   g_esrc);
    cudaGetSymbolAddress((void**)&Wh,     g_Wh);
    cudaGetSymbolAddress((void**)&Wl,     g_Wl);

    const int agg_blocks = (Nn + 15) / 16;
    const int n8 = Nn * HID / 8;
    const int WSZ = HID * HID;
    const dim3 gemm_grid((Nn + 127) / 128, 2);

    const int fill_blocks = (E + 255) / 256;
    const int f2h_blocks  = (n8 + 255) / 256;
    const int psp_blocks  = (4 * WSZ + 255) / 256;

    // ---- fused prep (fill + f2h + presplit) ----
    cudaMemsetAsync(cur, 0, Nn * sizeof(int));
    prep_kernel<<<fill_blocks + f2h_blocks + psp_blocks, 256>>>(
        src, dst, cur, esrc, E, fill_blocks,
        x, xh, n8, f2h_blocks,
        W1a, W1b, W2a, W2b, Wh, Wl);

    // ---- layer 1 ----
    gather_agg_h_kernel<<<agg_blocks, 256>>>(xh, esrc, cur, aggh, Nn);
    gemm_h_kernel<<<gemm_grid, 256>>>(aggh, Wh + 0 * WSZ, Wl + 0 * WSZ, b1a,
                                      nullptr, th, Nn);
    gemm_h_kernel<<<gemm_grid, 256>>>(th,   Wh + 1 * WSZ, Wl + 1 * WSZ, b1b,
                                      nullptr, hh, Nn);

    // ---- layer 2 ----
    gather_agg_h_kernel<<<agg_blocks, 256>>>(hh, esrc, cur, aggh, Nn);
    gemm_h_kernel<<<gemm_grid, 256>>>(aggh, Wh + 2 * WSZ, Wl + 2 * WSZ, b2a,
                                      nullptr, th, Nn);
    gemm_h_kernel<<<gemm_grid, 256>>>(th,   Wh + 3 * WSZ, Wl + 3 * WSZ, b2b,
                                      h2, nullptr, Nn);

    // ---- fused pool + head ----
    pool_head_kernel<<<G, 128>>>(h2, batch, Nn, Ws, bs, WlS, blS, WlP, blP,
                                 WnR, bnR, out, G);
}